// round 9
// baseline (speedup 1.0000x reference)
#include <cuda_runtime.h>
#include <cuda_bf16.h>
#include <cstdint>
#include <cstddef>

#define C_ 100
#define B_ 512
#define E_ 2048
#define F_ 128

#define NKT 32                 // k-tiles of 64
#define STAGE_BYTES 65536      // XH,XL,WH,WL tiles (16KB each)
#define DSMEM_SIZE (3 * STAGE_BYTES)

// ---------------- device scratch ----------------
__device__ __align__(1024) __nv_bfloat16 g_xh[B_ * E_];
__device__ __align__(1024) __nv_bfloat16 g_xl[B_ * E_];
__device__ __align__(1024) __nv_bfloat16 g_wh[(size_t)C_ * F_ * E_];
__device__ __align__(1024) __nv_bfloat16 g_wl[(size_t)C_ * F_ * E_];
__device__ float g_vraw[C_ * E_];
__device__ float g_nrm2p[C_ * 2];

// ---------------- helpers ----------------
__device__ __forceinline__ uint32_t smem_u32(const void* p) {
    uint32_t a;
    asm("{ .reg .u64 t; cvta.to.shared.u64 t, %1; cvt.u32.u64 %0, t; }" : "=r"(a) : "l"(p));
    return a;
}
__device__ __forceinline__ void cp16(uint32_t dst, const void* src) {
    asm volatile("cp.async.cg.shared.global [%0], [%1], 16;" :: "r"(dst), "l"(src) : "memory");
}

// =====================================================================
// split x into bf16 hi/lo
// =====================================================================
__global__ void split_x_kernel(const float* __restrict__ x) {
    int i = (blockIdx.x * 256 + threadIdx.x) * 2;
    float2 v = *(const float2*)&x[i];
    __nv_bfloat16 h0 = __float2bfloat16(v.x);
    __nv_bfloat16 h1 = __float2bfloat16(v.y);
    __nv_bfloat16 l0 = __float2bfloat16(v.x - __bfloat162float(h0));
    __nv_bfloat16 l1 = __float2bfloat16(v.y - __bfloat162float(h1));
    *(__nv_bfloat162*)&g_xh[i] = __halves2bfloat162(h0, h1);
    *(__nv_bfloat162*)&g_xl[i] = __halves2bfloat162(l0, l1);
}

// =====================================================================
// fused: W -> bf16 hi/lo split AND v_raw = W^T u with partial ||v||^2
// grid (C, 2), 256 threads; block owns e-range of 1024 (4 e per thread)
// =====================================================================
__global__ void wsplit_v_kernel(const float* __restrict__ W, const float* __restrict__ u) {
    int c = blockIdx.x, et = blockIdx.y;
    __shared__ float su[F_];
    __shared__ float red[8];
    int tid = threadIdx.x, lane = tid & 31, wrp = tid >> 5;

    if (tid < F_) su[tid] = u[c * F_ + tid];
    __syncthreads();

    int e0 = et * 1024 + tid * 4;
    const float* base = W + (size_t)c * F_ * E_ + e0;
    float v0 = 0.f, v1 = 0.f, v2 = 0.f, v3 = 0.f;
    #pragma unroll 8
    for (int f = 0; f < F_; f++) {
        float4 w = *(const float4*)(base + (size_t)f * E_);
        float uf = su[f];
        v0 = fmaf(w.x, uf, v0);
        v1 = fmaf(w.y, uf, v1);
        v2 = fmaf(w.z, uf, v2);
        v3 = fmaf(w.w, uf, v3);
        __nv_bfloat16 h0 = __float2bfloat16(w.x);
        __nv_bfloat16 h1 = __float2bfloat16(w.y);
        __nv_bfloat16 h2 = __float2bfloat16(w.z);
        __nv_bfloat16 h3 = __float2bfloat16(w.w);
        __nv_bfloat16 l0 = __float2bfloat16(w.x - __bfloat162float(h0));
        __nv_bfloat16 l1 = __float2bfloat16(w.y - __bfloat162float(h1));
        __nv_bfloat16 l2 = __float2bfloat16(w.z - __bfloat162float(h2));
        __nv_bfloat16 l3 = __float2bfloat16(w.w - __bfloat162float(h3));
        size_t oi = (size_t)(c * F_ + f) * E_ + e0;
        *(__nv_bfloat162*)&g_wh[oi]     = __halves2bfloat162(h0, h1);
        *(__nv_bfloat162*)&g_wh[oi + 2] = __halves2bfloat162(h2, h3);
        *(__nv_bfloat162*)&g_wl[oi]     = __halves2bfloat162(l0, l1);
        *(__nv_bfloat162*)&g_wl[oi + 2] = __halves2bfloat162(l2, l3);
    }
    float4 vv = make_float4(v0, v1, v2, v3);
    *(float4*)&g_vraw[c * E_ + e0] = vv;

    float loc = v0 * v0 + v1 * v1 + v2 * v2 + v3 * v3;
    #pragma unroll
    for (int o = 16; o; o >>= 1) loc += __shfl_xor_sync(0xffffffffu, loc, o);
    if (lane == 0) red[wrp] = loc;
    __syncthreads();
    if (tid == 0) {
        float s = 0.f;
        #pragma unroll
        for (int i = 0; i < 8; i++) s += red[i];
        g_nrm2p[c * 2 + et] = s;
    }
}

// =====================================================================
// Main kernel (proven R7 mainloop + in-kernel sigma):
// BM=128, BN=128, fused-term stages (64KB x 3), grid (4, C_).
//   Z[128,128] = xh*wh^T + xh*wl^T + xl*wh^T (fp32 accum, mma.sync bf16)
//   sigma = ||W v_hat|| computed concurrently on the idle FMA pipe
//   out = exp(-0.5 * sum_f (cent - (Z/sigma + bias))^2)
// =====================================================================
__global__ void __launch_bounds__(256, 1)
mm_kernel(const float* __restrict__ Wfp, const float* __restrict__ bias,
          const float* __restrict__ cent, float* __restrict__ out)
{
    extern __shared__ __align__(1024) char dsm[];
    __shared__ float s_bias[F_], s_cent[F_];
    __shared__ float part[128][4];
    __shared__ float sv[E_];
    __shared__ float red8[8];
    __shared__ float s_invs;

    int bt = blockIdx.x, c = blockIdx.y;
    int tid = threadIdx.x, wid = tid >> 5, lane = tid & 31;

    if (tid < F_) {
        s_bias[tid] = bias[c * F_ + tid];
        s_cent[tid] = cent[c * F_ + tid];
    }

    uint32_t dbase = smem_u32(dsm);
    int warp_m = wid >> 2, warp_n = wid & 3;

    float acc[4][4][4];
    #pragma unroll
    for (int mt = 0; mt < 4; mt++)
        #pragma unroll
        for (int nt = 0; nt < 4; nt++)
            #pragma unroll
            for (int q = 0; q < 4; q++) acc[mt][nt][q] = 0.f;

    int r0 = tid >> 3, kc = tid & 7;
    uint32_t dcol = (uint32_t)((kc ^ (r0 & 7)) * 16);
    uint32_t drow = (uint32_t)r0 * 128u + dcol;

    const __nv_bfloat16* xh_s = g_xh + (size_t)(bt * 128 + r0) * E_ + kc * 8;
    const __nv_bfloat16* xl_s = g_xl + (size_t)(bt * 128 + r0) * E_ + kc * 8;
    const __nv_bfloat16* wh_s = g_wh + (size_t)(c * 128 + r0) * E_ + kc * 8;
    const __nv_bfloat16* wl_s = g_wl + (size_t)(c * 128 + r0) * E_ + kc * 8;

#define STAGE_ADDR(s) (dbase + (uint32_t)(s) * (uint32_t)STAGE_BYTES)
#define LOAD_STAGE(slot, kt) do { \
    int _k0 = (kt) << 6; \
    uint32_t _da = STAGE_ADDR(slot) + drow; \
    _Pragma("unroll") \
    for (int _j = 0; _j < 4; _j++) { \
        cp16(_da          + _j * 4096u, xh_s + _k0 + (size_t)_j * 32 * E_); \
        cp16(_da + 16384u + _j * 4096u, xl_s + _k0 + (size_t)_j * 32 * E_); \
        cp16(_da + 32768u + _j * 4096u, wh_s + _k0 + (size_t)_j * 32 * E_); \
        cp16(_da + 49152u + _j * 4096u, wl_s + _k0 + (size_t)_j * 32 * E_); \
    } \
    asm volatile("cp.async.commit_group;" ::: "memory"); \
} while (0)

    LOAD_STAGE(0, 0);
    LOAD_STAGE(1, 1);

    // ---- load normalized v into smem (consumed by the sigma side-loop) ----
    {
        float n2 = g_nrm2p[c * 2] + g_nrm2p[c * 2 + 1];
        float invn = 1.f / fmaxf(sqrtf(n2), 1e-12f);
        int i = tid * 8;
        float4 a = *(const float4*)&g_vraw[c * E_ + i];
        float4 b = *(const float4*)&g_vraw[c * E_ + i + 4];
        a.x *= invn; a.y *= invn; a.z *= invn; a.w *= invn;
        b.x *= invn; b.y *= invn; b.z *= invn; b.w *= invn;
        *(float4*)&sv[i]     = a;
        *(float4*)&sv[i + 4] = b;
    }

    // sigma side-loop mapping: thread owns f-row tid>>1, e-half (tid&1)*32
    int frow = tid >> 1;
    int eh = (tid & 1) * 32;
    const float4* wrow = (const float4*)(Wfp + ((size_t)c * F_ + frow) * E_ + eh);
    float t_acc = 0.f;

    for (int it = 0; it < NKT; it++) {
        int s = it % 3;
        if (it == NKT - 1) asm volatile("cp.async.wait_group 0;" ::: "memory");
        else               asm volatile("cp.async.wait_group 1;" ::: "memory");
        __syncthreads();
        if (it + 2 < NKT) LOAD_STAGE((it + 2) % 3, it + 2);

        uint32_t XH = STAGE_ADDR(s);
        uint32_t XL = XH + 16384u;
        uint32_t WH = XH + 32768u;
        uint32_t WL = XH + 49152u;

        #pragma unroll
        for (int kk = 0; kk < 4; kk++) {
            uint32_t bh[4][2], bl[4][2];
            int mat = lane >> 3, rr = lane & 7;
            int kcb = kk * 2 + (mat & 1);
            #pragma unroll
            for (int g = 0; g < 2; g++) {
                int rown = warp_n * 32 + g * 16 + ((mat >> 1) << 3) + rr;
                uint32_t off = (uint32_t)rown * 128u + (uint32_t)((kcb ^ (rown & 7)) << 4);
                uint32_t q0, q1, q2, q3;
                asm volatile("ldmatrix.sync.aligned.m8n8.x4.shared.b16 {%0,%1,%2,%3}, [%4];"
                             : "=r"(q0), "=r"(q1), "=r"(q2), "=r"(q3) : "r"(WH + off));
                bh[g * 2 + 0][0] = q0; bh[g * 2 + 0][1] = q1;
                bh[g * 2 + 1][0] = q2; bh[g * 2 + 1][1] = q3;
                asm volatile("ldmatrix.sync.aligned.m8n8.x4.shared.b16 {%0,%1,%2,%3}, [%4];"
                             : "=r"(q0), "=r"(q1), "=r"(q2), "=r"(q3) : "r"(WL + off));
                bl[g * 2 + 0][0] = q0; bl[g * 2 + 0][1] = q1;
                bl[g * 2 + 1][0] = q2; bl[g * 2 + 1][1] = q3;
            }
            int kca = kk * 2 + (lane >> 4);
            #pragma unroll
            for (int mt = 0; mt < 4; mt++) {
                int rowm = warp_m * 64 + mt * 16 + ((lane >> 3) & 1) * 8 + (lane & 7);
                uint32_t off = (uint32_t)rowm * 128u + (uint32_t)((kca ^ (rowm & 7)) << 4);
                uint32_t a0, a1, a2, a3;
                asm volatile("ldmatrix.sync.aligned.m8n8.x4.shared.b16 {%0,%1,%2,%3}, [%4];"
                             : "=r"(a0), "=r"(a1), "=r"(a2), "=r"(a3) : "r"(XH + off));
                #pragma unroll
                for (int nt = 0; nt < 4; nt++) {
                    asm volatile(
                        "mma.sync.aligned.m16n8k16.row.col.f32.bf16.bf16.f32 "
                        "{%0,%1,%2,%3}, {%4,%5,%6,%7}, {%8,%9}, {%0,%1,%2,%3};"
                        : "+f"(acc[mt][nt][0]), "+f"(acc[mt][nt][1]),
                          "+f"(acc[mt][nt][2]), "+f"(acc[mt][nt][3])
                        : "r"(a0), "r"(a1), "r"(a2), "r"(a3),
                          "r"(bh[nt][0]), "r"(bh[nt][1]));
                    asm volatile(
                        "mma.sync.aligned.m16n8k16.row.col.f32.bf16.bf16.f32 "
                        "{%0,%1,%2,%3}, {%4,%5,%6,%7}, {%8,%9}, {%0,%1,%2,%3};"
                        : "+f"(acc[mt][nt][0]), "+f"(acc[mt][nt][1]),
                          "+f"(acc[mt][nt][2]), "+f"(acc[mt][nt][3])
                        : "r"(a0), "r"(a1), "r"(a2), "r"(a3),
                          "r"(bl[nt][0]), "r"(bl[nt][1]));
                }
                asm volatile("ldmatrix.sync.aligned.m8n8.x4.shared.b16 {%0,%1,%2,%3}, [%4];"
                             : "=r"(a0), "=r"(a1), "=r"(a2), "=r"(a3) : "r"(XL + off));
                #pragma unroll
                for (int nt = 0; nt < 4; nt++) {
                    asm volatile(
                        "mma.sync.aligned.m16n8k16.row.col.f32.bf16.bf16.f32 "
                        "{%0,%1,%2,%3}, {%4,%5,%6,%7}, {%8,%9}, {%0,%1,%2,%3};"
                        : "+f"(acc[mt][nt][0]), "+f"(acc[mt][nt][1]),
                          "+f"(acc[mt][nt][2]), "+f"(acc[mt][nt][3])
                        : "r"(a0), "r"(a1), "r"(a2), "r"(a3),
                          "r"(bh[nt][0]), "r"(bh[nt][1]));
                }
            }
        }

        // ---- sigma side-loop: t += W[frow, it*64+eh .. +32) . v_hat ----
        {
            const float4* wp = wrow + (it << 4);   // it*64 floats
            const float4* vp = (const float4*)&sv[(it << 6) + eh];
            #pragma unroll
            for (int q = 0; q < 8; q++) {
                float4 w4 = wp[q];
                float4 v4 = vp[q];
                t_acc = fmaf(w4.x, v4.x, t_acc);
                t_acc = fmaf(w4.y, v4.y, t_acc);
                t_acc = fmaf(w4.z, v4.z, t_acc);
                t_acc = fmaf(w4.w, v4.w, t_acc);
            }
        }
        // NOTE: no trailing __syncthreads — the top barrier of iteration
        // it+1 orders all iter-it reads before the slot-(it)%3 overwrite
        // issued at iteration it+1 (3 distinct stages).
    }
#undef LOAD_STAGE
#undef STAGE_ADDR

    // ---- sigma reduction: pairs (tid, tid^1) hold the two e-halves ----
    {
        float tf = t_acc + __shfl_xor_sync(0xffffffffu, t_acc, 1);
        float s2 = (tid & 1) ? 0.f : tf * tf;
        #pragma unroll
        for (int o = 16; o; o >>= 1) s2 += __shfl_xor_sync(0xffffffffu, s2, o);
        if (lane == 0) red8[wid] = s2;
    }
    __syncthreads();
    if (tid == 0) {
        float s = 0.f;
        #pragma unroll
        for (int i = 0; i < 8; i++) s += red8[i];
        s_invs = 1.f / sqrtf(s);
    }
    __syncthreads();

    // epilogue: dist2 partial per (m row, warp_n), then combine
    float inv_s = s_invs;
    int rgrp = lane >> 2, qc = lane & 3;
    #pragma unroll
    for (int mt = 0; mt < 4; mt++) {
        #pragma unroll
        for (int half = 0; half < 2; half++) {
            float sum = 0.f;
            #pragma unroll
            for (int nt = 0; nt < 4; nt++) {
                int f0 = warp_n * 32 + nt * 8 + qc * 2;
                float v0 = acc[mt][nt][half * 2 + 0];
                float v1 = acc[mt][nt][half * 2 + 1];
                float d0 = s_cent[f0]     - fmaf(v0, inv_s, s_bias[f0]);
                float d1 = s_cent[f0 + 1] - fmaf(v1, inv_s, s_bias[f0 + 1]);
                sum = fmaf(d0, d0, sum);
                sum = fmaf(d1, d1, sum);
            }
            sum += __shfl_xor_sync(0xffffffffu, sum, 1);
            sum += __shfl_xor_sync(0xffffffffu, sum, 2);
            if (qc == 0)
                part[warp_m * 64 + mt * 16 + half * 8 + rgrp][warp_n] = sum;
        }
    }
    __syncthreads();
    if (tid < 128) {
        float dist2 = part[tid][0] + part[tid][1] + part[tid][2] + part[tid][3];
        out[(size_t)(bt * 128 + tid) * C_ + c] = expf(-0.5f * dist2);
    }
}

// =====================================================================
// Host
// =====================================================================
extern "C" void kernel_launch(void* const* d_in, const int* in_sizes, int n_in,
                              void* d_out, int out_size)
{
    const float* x = (const float*)d_in[0];   // [512,2048]
    const float* W = (const float*)d_in[1];   // [100,128,2048]
    const float* b = (const float*)d_in[2];   // [100,128]
    const float* u = (const float*)d_in[3];   // [100,128]
    const float* c = (const float*)d_in[4];   // [100,128]
    float* out = (float*)d_out;               // [512,100]

    cudaFuncSetAttribute(mm_kernel, cudaFuncAttributeMaxDynamicSharedMemorySize, DSMEM_SIZE);

    split_x_kernel<<<(B_ * E_) / 512, 256>>>(x);
    wsplit_v_kernel<<<dim3(C_, 2), 256>>>(W, u);
    mm_kernel<<<dim3(4, C_), 256, DSMEM_SIZE>>>(W, b, c, out);
}

// round 10
// speedup vs baseline: 1.2434x; 1.2434x over previous
#include <cuda_runtime.h>
#include <cuda_bf16.h>
#include <cstdint>
#include <cstddef>

#define C_ 100
#define B_ 512
#define E_ 2048
#define F_ 128

#define NKT 32                 // k-tiles of 64
#define STAGE_BYTES 65536      // XH,XL,WH,WL tiles (16KB each)
#define DSMEM_SIZE (3 * STAGE_BYTES)

// ---------------- device scratch ----------------
__device__ __align__(1024) __nv_bfloat16 g_xh[B_ * E_];
__device__ __align__(1024) __nv_bfloat16 g_xl[B_ * E_];
__device__ __align__(1024) __nv_bfloat16 g_wh[(size_t)C_ * F_ * E_];
__device__ __align__(1024) __nv_bfloat16 g_wl[(size_t)C_ * F_ * E_];
__device__ float g_vraw[C_ * E_];
__device__ float g_nrm2p[C_ * 2];
__device__ float g_s2p[C_ * 64];

// ---------------- helpers ----------------
__device__ __forceinline__ uint32_t smem_u32(const void* p) {
    uint32_t a;
    asm("{ .reg .u64 t; cvta.to.shared.u64 t, %1; cvt.u32.u64 %0, t; }" : "=r"(a) : "l"(p));
    return a;
}
__device__ __forceinline__ void cp16(uint32_t dst, const void* src) {
    asm volatile("cp.async.cg.shared.global [%0], [%1], 16;" :: "r"(dst), "l"(src) : "memory");
}

// =====================================================================
// split x into bf16 hi/lo
// =====================================================================
__global__ void split_x_kernel(const float* __restrict__ x) {
    int i = (blockIdx.x * 256 + threadIdx.x) * 2;
    float2 v = *(const float2*)&x[i];
    __nv_bfloat16 h0 = __float2bfloat16(v.x);
    __nv_bfloat16 h1 = __float2bfloat16(v.y);
    __nv_bfloat16 l0 = __float2bfloat16(v.x - __bfloat162float(h0));
    __nv_bfloat16 l1 = __float2bfloat16(v.y - __bfloat162float(h1));
    *(__nv_bfloat162*)&g_xh[i] = __halves2bfloat162(h0, h1);
    *(__nv_bfloat162*)&g_xl[i] = __halves2bfloat162(l0, l1);
}

// =====================================================================
// fused: W -> bf16 hi/lo split AND v_raw = W^T u with partial ||v||^2
// =====================================================================
__global__ void wsplit_v_kernel(const float* __restrict__ W, const float* __restrict__ u) {
    int c = blockIdx.x, et = blockIdx.y;
    __shared__ float su[F_];
    __shared__ float red[8];
    int tid = threadIdx.x, lane = tid & 31, wrp = tid >> 5;

    if (tid < F_) su[tid] = u[c * F_ + tid];
    __syncthreads();

    int e0 = et * 1024 + tid * 4;
    const float* base = W + (size_t)c * F_ * E_ + e0;
    float v0 = 0.f, v1 = 0.f, v2 = 0.f, v3 = 0.f;
    #pragma unroll 8
    for (int f = 0; f < F_; f++) {
        float4 w = *(const float4*)(base + (size_t)f * E_);
        float uf = su[f];
        v0 = fmaf(w.x, uf, v0);
        v1 = fmaf(w.y, uf, v1);
        v2 = fmaf(w.z, uf, v2);
        v3 = fmaf(w.w, uf, v3);
        __nv_bfloat16 h0 = __float2bfloat16(w.x);
        __nv_bfloat16 h1 = __float2bfloat16(w.y);
        __nv_bfloat16 h2 = __float2bfloat16(w.z);
        __nv_bfloat16 h3 = __float2bfloat16(w.w);
        __nv_bfloat16 l0 = __float2bfloat16(w.x - __bfloat162float(h0));
        __nv_bfloat16 l1 = __float2bfloat16(w.y - __bfloat162float(h1));
        __nv_bfloat16 l2 = __float2bfloat16(w.z - __bfloat162float(h2));
        __nv_bfloat16 l3 = __float2bfloat16(w.w - __bfloat162float(h3));
        size_t oi = (size_t)(c * F_ + f) * E_ + e0;
        *(__nv_bfloat162*)&g_wh[oi]     = __halves2bfloat162(h0, h1);
        *(__nv_bfloat162*)&g_wh[oi + 2] = __halves2bfloat162(h2, h3);
        *(__nv_bfloat162*)&g_wl[oi]     = __halves2bfloat162(l0, l1);
        *(__nv_bfloat162*)&g_wl[oi + 2] = __halves2bfloat162(l2, l3);
    }
    float4 vv = make_float4(v0, v1, v2, v3);
    *(float4*)&g_vraw[c * E_ + e0] = vv;

    float loc = v0 * v0 + v1 * v1 + v2 * v2 + v3 * v3;
    #pragma unroll
    for (int o = 16; o; o >>= 1) loc += __shfl_xor_sync(0xffffffffu, loc, o);
    if (lane == 0) red[wrp] = loc;
    __syncthreads();
    if (tid == 0) {
        float s = 0.f;
        #pragma unroll
        for (int i = 0; i < 8; i++) s += red[i];
        g_nrm2p[c * 2 + et] = s;
    }
}

// =====================================================================
// t = W v_hat; partial sum of t^2. grid (C, 8), 256 threads.
// =====================================================================
__global__ void wv_kernel(const float* __restrict__ W) {
    int c = blockIdx.x, ft = blockIdx.y;
    __shared__ float sv[E_];
    __shared__ float s_inv;
    int tid = threadIdx.x, lane = tid & 31, wrp = tid >> 5;

    if (tid == 0)
        s_inv = 1.f / fmaxf(sqrtf(g_nrm2p[c * 2] + g_nrm2p[c * 2 + 1]), 1e-12f);
    __syncthreads();
    float inv = s_inv;
    for (int i = tid * 4; i < E_; i += 1024) {
        float4 v = *(const float4*)&g_vraw[c * E_ + i];
        v.x *= inv; v.y *= inv; v.z *= inv; v.w *= inv;
        *(float4*)&sv[i] = v;
    }
    __syncthreads();

    int f0 = ft * 16 + wrp * 2;
    const float* p0 = W + ((size_t)c * F_ + f0) * E_;
    const float* p1 = p0 + E_;
    float t0 = 0.f, t1 = 0.f;
    #pragma unroll 8
    for (int e = lane * 4; e < E_; e += 128) {
        float4 a = *(const float4*)(p0 + e);
        float4 b = *(const float4*)(p1 + e);
        float4 v = *(const float4*)&sv[e];
        t0 = fmaf(a.x, v.x, t0); t0 = fmaf(a.y, v.y, t0);
        t0 = fmaf(a.z, v.z, t0); t0 = fmaf(a.w, v.w, t0);
        t1 = fmaf(b.x, v.x, t1); t1 = fmaf(b.y, v.y, t1);
        t1 = fmaf(b.z, v.z, t1); t1 = fmaf(b.w, v.w, t1);
    }
    #pragma unroll
    for (int o = 16; o; o >>= 1) {
        t0 += __shfl_xor_sync(0xffffffffu, t0, o);
        t1 += __shfl_xor_sync(0xffffffffu, t1, o);
    }
    if (lane == 0) g_s2p[c * 64 + ft * 8 + wrp] = t0 * t0 + t1 * t1;
}

// =====================================================================
// Main kernel (R7 mainloop, trailing sync elided):
// BM=128, BN=128, fused-term stages (64KB x 3), grid (4, C_).
// =====================================================================
__global__ void __launch_bounds__(256, 1)
mm_kernel(const float* __restrict__ bias, const float* __restrict__ cent,
          float* __restrict__ out)
{
    extern __shared__ __align__(1024) char dsm[];
    __shared__ float s_bias[F_], s_cent[F_];
    __shared__ float part[128][4];
    __shared__ float s_invs;

    int bt = blockIdx.x, c = blockIdx.y;
    int tid = threadIdx.x, wid = tid >> 5, lane = tid & 31;

    if (tid < F_) {
        s_bias[tid] = bias[c * F_ + tid];
        s_cent[tid] = cent[c * F_ + tid];
    }
    if (wid == 0) {
        float s = g_s2p[c * 64 + lane] + g_s2p[c * 64 + 32 + lane];
        #pragma unroll
        for (int o = 16; o; o >>= 1) s += __shfl_xor_sync(0xffffffffu, s, o);
        if (lane == 0) s_invs = 1.f / sqrtf(s);
    }

    uint32_t dbase = smem_u32(dsm);
    int warp_m = wid >> 2, warp_n = wid & 3;

    float acc[4][4][4];
    #pragma unroll
    for (int mt = 0; mt < 4; mt++)
        #pragma unroll
        for (int nt = 0; nt < 4; nt++)
            #pragma unroll
            for (int q = 0; q < 4; q++) acc[mt][nt][q] = 0.f;

    int r0 = tid >> 3, kc = tid & 7;
    uint32_t dcol = (uint32_t)((kc ^ (r0 & 7)) * 16);
    uint32_t drow = (uint32_t)r0 * 128u + dcol;

    const __nv_bfloat16* xh_s = g_xh + (size_t)(bt * 128 + r0) * E_ + kc * 8;
    const __nv_bfloat16* xl_s = g_xl + (size_t)(bt * 128 + r0) * E_ + kc * 8;
    const __nv_bfloat16* wh_s = g_wh + (size_t)(c * 128 + r0) * E_ + kc * 8;
    const __nv_bfloat16* wl_s = g_wl + (size_t)(c * 128 + r0) * E_ + kc * 8;

#define STAGE_ADDR(s) (dbase + (uint32_t)(s) * (uint32_t)STAGE_BYTES)
#define LOAD_STAGE(slot, kt) do { \
    int _k0 = (kt) << 6; \
    uint32_t _da = STAGE_ADDR(slot) + drow; \
    _Pragma("unroll") \
    for (int _j = 0; _j < 4; _j++) { \
        cp16(_da          + _j * 4096u, xh_s + _k0 + (size_t)_j * 32 * E_); \
        cp16(_da + 16384u + _j * 4096u, xl_s + _k0 + (size_t)_j * 32 * E_); \
        cp16(_da + 32768u + _j * 4096u, wh_s + _k0 + (size_t)_j * 32 * E_); \
        cp16(_da + 49152u + _j * 4096u, wl_s + _k0 + (size_t)_j * 32 * E_); \
    } \
    asm volatile("cp.async.commit_group;" ::: "memory"); \
} while (0)

    LOAD_STAGE(0, 0);
    LOAD_STAGE(1, 1);

    for (int it = 0; it < NKT; it++) {
        int s = it % 3;
        if (it == NKT - 1) asm volatile("cp.async.wait_group 0;" ::: "memory");
        else               asm volatile("cp.async.wait_group 1;" ::: "memory");
        __syncthreads();
        if (it + 2 < NKT) LOAD_STAGE((it + 2) % 3, it + 2);

        uint32_t XH = STAGE_ADDR(s);
        uint32_t XL = XH + 16384u;
        uint32_t WH = XH + 32768u;
        uint32_t WL = XH + 49152u;

        #pragma unroll
        for (int kk = 0; kk < 4; kk++) {
            uint32_t bh[4][2], bl[4][2];
            int mat = lane >> 3, rr = lane & 7;
            int kcb = kk * 2 + (mat & 1);
            #pragma unroll
            for (int g = 0; g < 2; g++) {
                int rown = warp_n * 32 + g * 16 + ((mat >> 1) << 3) + rr;
                uint32_t off = (uint32_t)rown * 128u + (uint32_t)((kcb ^ (rown & 7)) << 4);
                uint32_t q0, q1, q2, q3;
                asm volatile("ldmatrix.sync.aligned.m8n8.x4.shared.b16 {%0,%1,%2,%3}, [%4];"
                             : "=r"(q0), "=r"(q1), "=r"(q2), "=r"(q3) : "r"(WH + off));
                bh[g * 2 + 0][0] = q0; bh[g * 2 + 0][1] = q1;
                bh[g * 2 + 1][0] = q2; bh[g * 2 + 1][1] = q3;
                asm volatile("ldmatrix.sync.aligned.m8n8.x4.shared.b16 {%0,%1,%2,%3}, [%4];"
                             : "=r"(q0), "=r"(q1), "=r"(q2), "=r"(q3) : "r"(WL + off));
                bl[g * 2 + 0][0] = q0; bl[g * 2 + 0][1] = q1;
                bl[g * 2 + 1][0] = q2; bl[g * 2 + 1][1] = q3;
            }
            int kca = kk * 2 + (lane >> 4);
            #pragma unroll
            for (int mt = 0; mt < 4; mt++) {
                int rowm = warp_m * 64 + mt * 16 + ((lane >> 3) & 1) * 8 + (lane & 7);
                uint32_t off = (uint32_t)rowm * 128u + (uint32_t)((kca ^ (rowm & 7)) << 4);
                uint32_t a0, a1, a2, a3;
                asm volatile("ldmatrix.sync.aligned.m8n8.x4.shared.b16 {%0,%1,%2,%3}, [%4];"
                             : "=r"(a0), "=r"(a1), "=r"(a2), "=r"(a3) : "r"(XH + off));
                #pragma unroll
                for (int nt = 0; nt < 4; nt++) {
                    asm volatile(
                        "mma.sync.aligned.m16n8k16.row.col.f32.bf16.bf16.f32 "
                        "{%0,%1,%2,%3}, {%4,%5,%6,%7}, {%8,%9}, {%0,%1,%2,%3};"
                        : "+f"(acc[mt][nt][0]), "+f"(acc[mt][nt][1]),
                          "+f"(acc[mt][nt][2]), "+f"(acc[mt][nt][3])
                        : "r"(a0), "r"(a1), "r"(a2), "r"(a3),
                          "r"(bh[nt][0]), "r"(bh[nt][1]));
                    asm volatile(
                        "mma.sync.aligned.m16n8k16.row.col.f32.bf16.bf16.f32 "
                        "{%0,%1,%2,%3}, {%4,%5,%6,%7}, {%8,%9}, {%0,%1,%2,%3};"
                        : "+f"(acc[mt][nt][0]), "+f"(acc[mt][nt][1]),
                          "+f"(acc[mt][nt][2]), "+f"(acc[mt][nt][3])
                        : "r"(a0), "r"(a1), "r"(a2), "r"(a3),
                          "r"(bl[nt][0]), "r"(bl[nt][1]));
                }
                asm volatile("ldmatrix.sync.aligned.m8n8.x4.shared.b16 {%0,%1,%2,%3}, [%4];"
                             : "=r"(a0), "=r"(a1), "=r"(a2), "=r"(a3) : "r"(XL + off));
                #pragma unroll
                for (int nt = 0; nt < 4; nt++) {
                    asm volatile(
                        "mma.sync.aligned.m16n8k16.row.col.f32.bf16.bf16.f32 "
                        "{%0,%1,%2,%3}, {%4,%5,%6,%7}, {%8,%9}, {%0,%1,%2,%3};"
                        : "+f"(acc[mt][nt][0]), "+f"(acc[mt][nt][1]),
                          "+f"(acc[mt][nt][2]), "+f"(acc[mt][nt][3])
                        : "r"(a0), "r"(a1), "r"(a2), "r"(a3),
                          "r"(bh[nt][0]), "r"(bh[nt][1]));
                }
            }
        }
        // trailing __syncthreads elided: with 3 distinct stages, the top
        // barrier of iteration it+1 orders all iter-it smem reads before
        // the slot overwrite issued at iteration it+1 (validated in R9).
    }
#undef LOAD_STAGE
#undef STAGE_ADDR

    // epilogue
    float inv_s = s_invs;
    int rgrp = lane >> 2, qc = lane & 3;
    #pragma unroll
    for (int mt = 0; mt < 4; mt++) {
        #pragma unroll
        for (int half = 0; half < 2; half++) {
            float sum = 0.f;
            #pragma unroll
            for (int nt = 0; nt < 4; nt++) {
                int f0 = warp_n * 32 + nt * 8 + qc * 2;
                float v0 = acc[mt][nt][half * 2 + 0];
                float v1 = acc[mt][nt][half * 2 + 1];
                float d0 = s_cent[f0]     - fmaf(v0, inv_s, s_bias[f0]);
                float d1 = s_cent[f0 + 1] - fmaf(v1, inv_s, s_bias[f0 + 1]);
                sum = fmaf(d0, d0, sum);
                sum = fmaf(d1, d1, sum);
            }
            sum += __shfl_xor_sync(0xffffffffu, sum, 1);
            sum += __shfl_xor_sync(0xffffffffu, sum, 2);
            if (qc == 0)
                part[warp_m * 64 + mt * 16 + half * 8 + rgrp][warp_n] = sum;
        }
    }
    __syncthreads();
    if (tid < 128) {
        float dist2 = part[tid][0] + part[tid][1] + part[tid][2] + part[tid][3];
        out[(size_t)(bt * 128 + tid) * C_ + c] = expf(-0.5f * dist2);
    }
}

// =====================================================================
// Host
// =====================================================================
extern "C" void kernel_launch(void* const* d_in, const int* in_sizes, int n_in,
                              void* d_out, int out_size)
{
    const float* x = (const float*)d_in[0];   // [512,2048]
    const float* W = (const float*)d_in[1];   // [100,128,2048]
    const float* b = (const float*)d_in[2];   // [100,128]
    const float* u = (const float*)d_in[3];   // [100,128]
    const float* c = (const float*)d_in[4];   // [100,128]
    float* out = (float*)d_out;               // [512,100]

    cudaFuncSetAttribute(mm_kernel, cudaFuncAttributeMaxDynamicSharedMemorySize, DSMEM_SIZE);

    split_x_kernel<<<(B_ * E_) / 512, 256>>>(x);
    wsplit_v_kernel<<<dim3(C_, 2), 256>>>(W, u);
    wv_kernel<<<dim3(C_, 8), 256>>>(W);
    mm_kernel<<<dim3(4, C_), 256, DSMEM_SIZE>>>(b, c, out);
}